// round 4
// baseline (speedup 1.0000x reference)
#include <cuda_runtime.h>

// Fixed shapes
#define HH   512
#define WW   512
#define HWSZ (HH * WW)          // 262144 = 2^18
#define BB   4
#define CC   21
#define NPIX (BB * HWSZ)        // 1048576
#define TILE 64                 // 64x64 tiles
#define TPP  (TILE * TILE)      // 4096
#define NTILES (BB * 8 * 8)     // 256
#define FBLOCKS 4096
#define MAXMERGE 32768          // >= total boundary edges (28672)

// Static device scratch
__device__ int           g_labels[NPIX];
__device__ int           g_counts[NPIX];   // valid only at local-root indices
__device__ unsigned char g_tgt[NPIX];
__device__ float         g_partial[FBLOCKS];
__device__ int           g_merged[MAXMERGE];
__device__ int           g_nm;
__device__ int           g_is32;

// ---------------------------------------------------------------------------
// dtype detect (int32 vs int64 targets) + reset merge counter.
// int64 values 0..20 have zero high words; int32 words nonzero w.p. 20/21
// -> P(misdetect) = 21^-256 ~ 0.
// ---------------------------------------------------------------------------
__global__ void k_detect(const unsigned* __restrict__ t) {
    unsigned v = t[2 * threadIdx.x + 1];
    int any = __syncthreads_or(v != 0u);
    if (threadIdx.x == 0) { g_is32 = any; g_nm = 0; }
}

// ---------------------------------------------------------------------------
// Shared-memory union-find (tile-local)
// ---------------------------------------------------------------------------
__device__ __forceinline__ int sfind(volatile int* lab, int x) {
    int y = lab[x];
    while (y != x) { x = y; y = lab[x]; }
    return x;
}
__device__ __forceinline__ void sunite(int* lab, int a, int b) {
    while (true) {
        a = sfind(lab, a);
        b = sfind(lab, b);
        if (a == b) return;
        int mx = a > b ? a : b;
        int mn = a > b ? b : a;
        int old = atomicMin(&lab[mx], mn);
        if (old == mx) return;
        a = old; b = mn;
    }
}

// Global union-find; records every root that stops being a root.
__device__ __forceinline__ int gfind(int x) {
    int y = g_labels[x];
    while (y != x) { x = y; y = g_labels[x]; }
    return x;
}
__device__ __forceinline__ void gunite(int a, int b) {
    while (true) {
        a = gfind(a);
        b = gfind(b);
        if (a == b) return;
        int mx = a > b ? a : b;
        int mn = a > b ? b : a;
        int old = atomicMin(&g_labels[mx], mn);
        if (old == mx) {                    // mx just ceased to be a root
            int s = atomicAdd(&g_nm, 1);
            g_merged[s] = mx;
            return;
        }
        a = old; b = mn;
    }
}

// ---------------------------------------------------------------------------
// Fused normalize + tile-local CCL + local size histogram.
// 64x64 tile, 256 threads, 16 px/thread, 33KB smem.
// Writes: g_tgt, g_labels (pixel -> global index of tile-local root),
//         g_counts[root] = local component size (fg pixel count).
// ---------------------------------------------------------------------------
__global__ void __launch_bounds__(256) k_local(const void* __restrict__ t) {
    __shared__ unsigned char st[TPP];
    __shared__ int           sl[TPP];
    __shared__ int           scount[TPP];

    int tile = blockIdx.x;
    int img  = tile >> 6;
    int ty   = (tile >> 3) & 7;
    int tx   = tile & 7;
    int base = img * HWSZ + (ty * TILE) * WW + tx * TILE;
    int is32 = g_is32;

#pragma unroll
    for (int k = 0; k < 16; k++) {
        int i  = threadIdx.x + k * 256;
        int gp = base + (i >> 6) * WW + (i & 63);
        int v  = is32 ? ((const int*)t)[gp]
                      : (int)((const long long*)t)[gp];
        st[i] = (unsigned char)v;
        sl[i] = i;
        scount[i] = 0;
        g_tgt[gp] = (unsigned char)v;
    }
    __syncthreads();

#pragma unroll
    for (int k = 0; k < 16; k++) {
        int i = threadIdx.x + k * 256;
        int c = st[i];
        if (c) {
            if ((i & 63) != 63 && st[i + 1]  == c) sunite(sl, i, i + 1);
            if (i < TPP - TILE && st[i + 64] == c) sunite(sl, i, i + 64);
        }
    }
    __syncthreads();

    // compress, write global labels, histogram fg pixels onto local roots
#pragma unroll
    for (int k = 0; k < 16; k++) {
        int i  = threadIdx.x + k * 256;
        int r  = sfind(sl, i);
        int gp = base + (i >> 6) * WW + (i & 63);
        g_labels[gp] = base + (r >> 6) * WW + (r & 63);
        if (st[i]) atomicAdd(&scount[r], 1);
    }
    __syncthreads();

    // root threads export their component size
#pragma unroll
    for (int k = 0; k < 16; k++) {
        int i = threadIdx.x + k * 256;
        if (sl[i] == i) {
            int gp = base + (i >> 6) * WW + (i & 63);
            g_counts[gp] = scount[i];
        }
    }
}

// ---------------------------------------------------------------------------
// Cross-tile boundary merges: 7 vertical + 7 horizontal seams per image,
// 512 edges each -> 28672 total. Unions start from the stored tile roots.
// ---------------------------------------------------------------------------
#define EDGES_PER_DIR (7 * 512)
#define EDGES_PER_IMG (2 * EDGES_PER_DIR)
#define NEDGES (BB * EDGES_PER_IMG)

__global__ void k_boundary() {
    int e = blockIdx.x * blockDim.x + threadIdx.x;
    if (e >= NEDGES) return;
    int img = e / EDGES_PER_IMG;
    int rem = e % EDGES_PER_IMG;
    int dir = rem / EDGES_PER_DIR;
    int k   = rem % EDGES_PER_DIR;
    int b   = k >> 9;
    int t   = k & 511;

    int p, q;
    if (dir == 0) {            // vertical seam between tile columns b, b+1
        int x = b * TILE + (TILE - 1);
        p = img * HWSZ + t * WW + x;
        q = p + 1;
    } else {                   // horizontal seam between tile rows b, b+1
        int y = b * TILE + (TILE - 1);
        p = img * HWSZ + y * WW + t;
        q = p + WW;
    }
    int c = g_tgt[p];
    if (c && g_tgt[q] == c) gunite(g_labels[p], g_labels[q]);
}

// ---------------------------------------------------------------------------
// Sparse fixup: each merged local root adds its local size to its final root.
// ---------------------------------------------------------------------------
__global__ void k_fixup() {
    int i = blockIdx.x * blockDim.x + threadIdx.x;
    if (i >= g_nm) return;
    int r = g_merged[i];
    int f = gfind(r);
    atomicAdd(&g_counts[f], g_counts[r]);
}

// ---------------------------------------------------------------------------
// Fused CE + weight + block reduction; single pass over 88MB logits.
// ---------------------------------------------------------------------------
__global__ void __launch_bounds__(256) k_final(const float* __restrict__ logits) {
    __shared__ float sh[256];
    const float inv_log501 = 0.16085946f;   // 1/ln(501)

    int p   = blockIdx.x * 256 + threadIdx.x;
    int b   = p >> 18;
    int pix = p & (HWSZ - 1);
    const float* base = logits + ((size_t)b * CC) * HWSZ + pix;

    int ti = g_tgt[p];
    float v[CC];
    float m = -1e30f, tv = 0.f;
#pragma unroll
    for (int c = 0; c < CC; c++) {
        v[c] = base[(size_t)c * HWSZ];
        m = fmaxf(m, v[c]);
        if (c == ti) tv = v[c];
    }
    float s = 0.f;
#pragma unroll
    for (int c = 0; c < CC; c++) s += __expf(v[c] - m);

    float ce = m + __logf(s) - tv;

    float wgt = 1.f;
    if (ti > 0) {
        int r = g_labels[p];              // tile-local root
        int y = g_labels[r];              // follow merge chain (usually r==y)
        while (y != r) { r = y; y = g_labels[r]; }
        int sz = g_counts[r];
        if (sz < 500)
            wgt = 3.f * __logf((float)sz + 1.f) * inv_log501;
    }

    sh[threadIdx.x] = ce * wgt;
    __syncthreads();
#pragma unroll
    for (int s2 = 128; s2 > 0; s2 >>= 1) {
        if (threadIdx.x < s2) sh[threadIdx.x] += sh[threadIdx.x + s2];
        __syncthreads();
    }
    if (threadIdx.x == 0) g_partial[blockIdx.x] = sh[0];
}

// Deterministic final reduction
__global__ void k_reduce(float* __restrict__ out) {
    __shared__ float sh[256];
    float a = 0.f;
    for (int i = threadIdx.x; i < FBLOCKS; i += 256) a += g_partial[i];
    sh[threadIdx.x] = a;
    __syncthreads();
#pragma unroll
    for (int s = 128; s > 0; s >>= 1) {
        if (threadIdx.x < s) sh[threadIdx.x] += sh[threadIdx.x + s];
        __syncthreads();
    }
    if (threadIdx.x == 0) out[0] = sh[0] * (1.f / (float)NPIX);
}

// ---------------------------------------------------------------------------
extern "C" void kernel_launch(void* const* d_in, const int* in_sizes, int n_in,
                              void* d_out, int out_size) {
    const float* logits = (const float*)d_in[0];
    const void*  tgt    = d_in[1];
    float*       out    = (float*)d_out;

    const int T = 256;

    k_detect  <<<1, T>>>((const unsigned*)tgt);
    k_local   <<<NTILES, T>>>(tgt);
    k_boundary<<<(NEDGES + T - 1) / T, T>>>();
    k_fixup   <<<MAXMERGE / T, T>>>();
    k_final   <<<FBLOCKS, T>>>(logits);
    k_reduce  <<<1, T>>>(out);
}

// round 5
// speedup vs baseline: 1.1422x; 1.1422x over previous
#include <cuda_runtime.h>

// Fixed shapes
#define HH   512
#define WW   512
#define HWSZ (HH * WW)          // 262144 = 2^18
#define BB   4
#define CC   21
#define NPIX (BB * HWSZ)        // 1048576
#define TILE 32                 // 32x32 tiles
#define TPP  (TILE * TILE)      // 1024
#define NTILES (BB * 16 * 16)   // 1024 blocks
#define FBLOCKS 2048            // k_final blocks (2 px/thread)
#define MAXMERGE 65536          // >= max possible merges (61440 edges)

// Static device scratch
__device__ int           g_labels[NPIX];
__device__ int           g_counts[NPIX];   // valid at local-root indices
__device__ unsigned char g_tgt[NPIX];
__device__ float         g_partial[FBLOCKS];
__device__ int           g_merged[MAXMERGE];
__device__ int           g_nm;
__device__ unsigned      g_cnt_boundary;
__device__ unsigned      g_cnt_final;

// ---------------------------------------------------------------------------
// Shared-memory union-find (tile-local)
// ---------------------------------------------------------------------------
__device__ __forceinline__ int sfind(volatile int* lab, int x) {
    int y = lab[x];
    while (y != x) { x = y; y = lab[x]; }
    return x;
}
__device__ __forceinline__ void sunite(int* lab, int a, int b) {
    while (true) {
        a = sfind(lab, a);
        b = sfind(lab, b);
        if (a == b) return;
        int mx = a > b ? a : b;
        int mn = a > b ? b : a;
        int old = atomicMin(&lab[mx], mn);
        if (old == mx) return;
        a = old; b = mn;
    }
}
// Global union-find; records roots that cease to be roots.
__device__ __forceinline__ int gfind(int x) {
    int y = g_labels[x];
    while (y != x) { x = y; y = g_labels[x]; }
    return x;
}
__device__ __forceinline__ void gunite(int a, int b) {
    while (true) {
        a = gfind(a);
        b = gfind(b);
        if (a == b) return;
        int mx = a > b ? a : b;
        int mn = a > b ? b : a;
        int old = atomicMin(&g_labels[mx], mn);
        if (old == mx) {
            int s = atomicAdd(&g_nm, 1);
            g_merged[s] = mx;
            return;
        }
        a = old; b = mn;
    }
}

// ---------------------------------------------------------------------------
// k_local: fused dtype-detect + normalize + tile-local CCL + size histogram.
// 32x32 tile, 256 threads (4 px/thread), ~9.2KB smem, 1024 blocks.
// ---------------------------------------------------------------------------
__global__ void __launch_bounds__(256) k_local(const void* __restrict__ t) {
    __shared__ unsigned char st[TPP];
    __shared__ int           sl[TPP];
    __shared__ int           scount[TPP];

    // Per-block dtype self-detection: first 256 elements of the buffer.
    // int64 values 0..20 -> all high words zero; int32 -> nonzero w.p. 20/21
    // per word => P(misdetect) = 21^-256 ~ 0. Word indices 1..511 are in
    // range for both dtypes.
    unsigned hw = ((const unsigned*)t)[2 * threadIdx.x + 1];
    int is32 = __syncthreads_or(hw != 0u);

    if (blockIdx.x == 0 && threadIdx.x == 0) {
        g_nm = 0; g_cnt_boundary = 0; g_cnt_final = 0;
    }

    int tile = blockIdx.x;
    int img  = tile >> 8;                 // 256 tiles per image
    int ty   = (tile >> 4) & 15;
    int tx   = tile & 15;
    int base = img * HWSZ + (ty * TILE) * WW + tx * TILE;

#pragma unroll
    for (int k = 0; k < 4; k++) {
        int i  = threadIdx.x + k * 256;
        int gp = base + (i >> 5) * WW + (i & 31);
        int v  = is32 ? ((const int*)t)[gp]
                      : (int)((const long long*)t)[gp];
        st[i] = (unsigned char)v;
        sl[i] = i;
        scount[i] = 0;
        g_tgt[gp] = (unsigned char)v;
    }
    __syncthreads();

#pragma unroll
    for (int k = 0; k < 4; k++) {
        int i = threadIdx.x + k * 256;
        int c = st[i];
        if (c) {
            if ((i & 31) != 31 && st[i + 1]  == c) sunite(sl, i, i + 1);
            if (i < TPP - TILE && st[i + 32] == c) sunite(sl, i, i + 32);
        }
    }
    __syncthreads();

    // compress, write global labels, histogram fg pixels onto local roots
#pragma unroll
    for (int k = 0; k < 4; k++) {
        int i  = threadIdx.x + k * 256;
        int r  = sfind(sl, i);
        int gp = base + (i >> 5) * WW + (i & 31);
        g_labels[gp] = base + (r >> 5) * WW + (r & 31);
        if (st[i]) atomicAdd(&scount[r], 1);
    }
    __syncthreads();

    // roots export their local component size
#pragma unroll
    for (int k = 0; k < 4; k++) {
        int i = threadIdx.x + k * 256;
        if (sl[i] == i) {
            int gp = base + (i >> 5) * WW + (i & 31);
            g_counts[gp] = scount[i];
        }
    }
}

// ---------------------------------------------------------------------------
// k_boundary: cross-tile merges (15 v-seams + 15 h-seams per image, 512 edges
// each -> 61440 edges, 240 blocks). Last block performs the sparse count
// fixup after all unions are globally visible.
// ---------------------------------------------------------------------------
#define EDGES_PER_DIR (15 * 512)
#define EDGES_PER_IMG (2 * EDGES_PER_DIR)
#define NEDGES (BB * EDGES_PER_IMG)        // 61440
#define BBLOCKS (NEDGES / 256)             // 240

__global__ void __launch_bounds__(256) k_boundary() {
    int e = blockIdx.x * 256 + threadIdx.x;
    int img = e / EDGES_PER_IMG;
    int rem = e % EDGES_PER_IMG;
    int dir = rem / EDGES_PER_DIR;
    int k   = rem % EDGES_PER_DIR;
    int b   = k >> 9;
    int t   = k & 511;

    int p, q;
    if (dir == 0) {            // vertical seam between tile cols b, b+1
        int x = b * TILE + (TILE - 1);
        p = img * HWSZ + t * WW + x;
        q = p + 1;
    } else {                   // horizontal seam between tile rows b, b+1
        int y = b * TILE + (TILE - 1);
        p = img * HWSZ + y * WW + t;
        q = p + WW;
    }
    int c = g_tgt[p];
    if (c && g_tgt[q] == c) gunite(g_labels[p], g_labels[q]);

    // last-block fixup
    __shared__ int isLast;
    __syncthreads();
    if (threadIdx.x == 0) {
        __threadfence();
        unsigned r = atomicAdd(&g_cnt_boundary, 1u);
        isLast = (r == BBLOCKS - 1);
    }
    __syncthreads();
    if (isLast) {
        int nm = g_nm;
        for (int i = threadIdx.x; i < nm; i += 256) {
            int r = g_merged[i];
            int f = gfind(r);
            atomicAdd(&g_counts[f], g_counts[r]);
        }
    }
}

// ---------------------------------------------------------------------------
// k_final: fused CE + weight + block reduction, 2 pixels/thread (float2),
// single pass over the 88MB logits. Last block does the deterministic
// final reduction and writes the mean.
// ---------------------------------------------------------------------------
__device__ __forceinline__ float region_weight(int ti, int p) {
    const float inv_log501 = 0.16085946f;   // 1/ln(501)
    float wgt = 1.f;
    if (ti > 0) {
        int r = g_labels[p];               // tile-local root
        int y = g_labels[r];
        while (y != r) { r = y; y = g_labels[r]; }
        int sz = g_counts[r];
        if (sz < 500)
            wgt = 3.f * __logf((float)sz + 1.f) * inv_log501;
    }
    return wgt;
}

__global__ void __launch_bounds__(256) k_final(const float* __restrict__ logits,
                                               float* __restrict__ out) {
    __shared__ float sh[256];

    int p0  = (blockIdx.x * 256 + threadIdx.x) * 2;
    int b   = p0 >> 18;
    int pix = p0 & (HWSZ - 1);
    const float2* base =
        (const float2*)(logits + ((size_t)b * CC) * HWSZ + pix);

    int t0 = g_tgt[p0];
    int t1 = g_tgt[p0 + 1];

    float2 v[CC];
    float m0 = -1e30f, m1 = -1e30f, tv0 = 0.f, tv1 = 0.f;
#pragma unroll
    for (int c = 0; c < CC; c++) {
        v[c] = base[(size_t)c * (HWSZ / 2)];
        m0 = fmaxf(m0, v[c].x);
        m1 = fmaxf(m1, v[c].y);
        if (c == t0) tv0 = v[c].x;
        if (c == t1) tv1 = v[c].y;
    }
    float s0 = 0.f, s1 = 0.f;
#pragma unroll
    for (int c = 0; c < CC; c++) {
        s0 += __expf(v[c].x - m0);
        s1 += __expf(v[c].y - m1);
    }
    float ce0 = m0 + __logf(s0) - tv0;
    float ce1 = m1 + __logf(s1) - tv1;

    float acc = ce0 * region_weight(t0, p0) + ce1 * region_weight(t1, p0 + 1);

    sh[threadIdx.x] = acc;
    __syncthreads();
#pragma unroll
    for (int s2 = 128; s2 > 0; s2 >>= 1) {
        if (threadIdx.x < s2) sh[threadIdx.x] += sh[threadIdx.x + s2];
        __syncthreads();
    }
    if (threadIdx.x == 0) g_partial[blockIdx.x] = sh[0];

    // last-block deterministic final reduction
    __shared__ int isLast;
    if (threadIdx.x == 0) {
        __threadfence();
        unsigned r = atomicAdd(&g_cnt_final, 1u);
        isLast = (r == FBLOCKS - 1);
    }
    __syncthreads();
    if (isLast) {
        float a = 0.f;
        for (int i = threadIdx.x; i < FBLOCKS; i += 256) a += g_partial[i];
        sh[threadIdx.x] = a;
        __syncthreads();
#pragma unroll
        for (int s2 = 128; s2 > 0; s2 >>= 1) {
            if (threadIdx.x < s2) sh[threadIdx.x] += sh[threadIdx.x + s2];
            __syncthreads();
        }
        if (threadIdx.x == 0) out[0] = sh[0] * (1.f / (float)NPIX);
    }
}

// ---------------------------------------------------------------------------
extern "C" void kernel_launch(void* const* d_in, const int* in_sizes, int n_in,
                              void* d_out, int out_size) {
    const float* logits = (const float*)d_in[0];
    const void*  tgt    = d_in[1];
    float*       out    = (float*)d_out;

    k_local   <<<NTILES, 256>>>(tgt);
    k_boundary<<<BBLOCKS, 256>>>();
    k_final   <<<FBLOCKS, 256>>>(logits, out);
}